// round 6
// baseline (speedup 1.0000x reference)
#include <cuda_runtime.h>

// -------- static scratch (no allocations allowed) --------
// Zero-initialized at module load; reset by K2/K3 each call so every call
// (including graph replays) observes zeroed counters.
#define CAPR 64
#define CAPC 64
#define MAXN 4096

__device__ int   g_cnt_row[MAXN];     // CSR bucket fill counts
__device__ float g_rowsum[MAXN];      // S_k = sum of row k's scaled weights
__device__ int   g_colbuf[MAXN * CAPR];
__device__ float g_valbuf[MAXN * CAPR];   // stores -v
__device__ int   g_cnt_col[MAXN];     // contributor-list fill counts
__device__ int   g_kbuf[MAXN * CAPC];     // contributor source row k
__device__ float g_cfbuf[MAXN * CAPC];    // contributor coefficient (-v)

// ============ K1: bin the CM COO by row (CSR) and by column (contributors) ==
__global__ void k1_bin(const int* __restrict__ row,
                       const int* __restrict__ col,
                       const float* __restrict__ data,
                       const float* __restrict__ cmw, int nnz) {
    int t = blockIdx.x * blockDim.x + threadIdx.x;
    if (t >= nnz) return;
    int r = row[t];
    int c = col[t];
    float v = data[t] * cmw[r];
    // CSR row bucket (entry value of Lcm row r at col c is -v)
    int s = atomicAdd(&g_cnt_row[r], 1);
    if (s < CAPR) {
        g_colbuf[r * CAPR + s] = c;
        g_valbuf[r * CAPR + s] = -v;
    }
    atomicAdd(&g_rowsum[r], v);
    // contributor bucket: output row c receives coefficient Lcm[r,c] ∋ -v
    int s2 = atomicAdd(&g_cnt_col[c], 1);
    if (s2 < CAPC) {
        g_kbuf[c * CAPC + s2]  = r;
        g_cfbuf[c * CAPC + s2] = -v;
    }
}

// ============ K2: build each output row of A = Lcm^T Lcm in smem, store once
__global__ void k2_rows(float* __restrict__ A, int n) {
    __shared__ float rowbuf[MAXN];
    __shared__ int   skk[CAPC + 1];
    __shared__ float scf[CAPC + 1];
    int a = blockIdx.x;
    int tid = threadIdx.x;

    for (int i = tid; i < n; i += blockDim.x) rowbuf[i] = 0.f;

    int cc = g_cnt_col[a];
    if (cc > CAPC) cc = CAPC;
    for (int i = tid; i < cc; i += blockDim.x) {
        skk[i] = g_kbuf[a * CAPC + i];
        scf[i] = g_cfbuf[a * CAPC + i];
    }
    if (tid == 0) {
        // implicit contributor: virtual diagonal entry (a, +S_a)
        skk[cc] = a;
        scf[cc] = g_rowsum[a];
        g_cnt_col[a] = 0;   // reset for next call
    }
    __syncthreads();

    int tot  = cc + 1;
    int warp = tid >> 5, lane = tid & 31, nw = blockDim.x >> 5;
    for (int it = warp; it < tot; it += nw) {
        int   k    = skk[it];
        float coef = scf[it];
        int ck = g_cnt_row[k];
        if (ck > CAPR) ck = CAPR;
        for (int j = lane; j < ck; j += 32)
            atomicAdd(&rowbuf[g_colbuf[k * CAPR + j]],
                      coef * g_valbuf[k * CAPR + j]);
        if (lane == 0)   // virtual diagonal entry of source row k
            atomicAdd(&rowbuf[k], coef * g_rowsum[k]);
    }
    __syncthreads();

    float4* dst = (float4*)(A + (size_t)a * n);
    const float4* src = (const float4*)rowbuf;
    int n4 = n >> 2;
    for (int i = tid; i < n4; i += blockDim.x) dst[i] = src[i];
}

// ============ K3: LOC + IU symmetrized Laplacians, diag + b, scratch reset ==
__global__ void k3_rest(float* __restrict__ A, float* __restrict__ bvec,
                        int n, long total,
                        const int* __restrict__ locInd,
                        const float* __restrict__ locFl,
                        const float* __restrict__ locw,
                        int mloc, const int* __restrict__ widthp,
                        const int* __restrict__ iuInd,
                        const float* __restrict__ iuFl,
                        const int* __restrict__ iuNb,
                        const float* __restrict__ iuw,
                        int miu,
                        const float* __restrict__ ku,
                        const float* __restrict__ conf,
                        const float* __restrict__ lmb,
                        const float* __restrict__ known,
                        const float* __restrict__ kToU,
                        int nbLoc, int nbIu) {
    int b = blockIdx.x;

    if (b < nbLoc) {
        int mi = b * blockDim.x + threadIdx.x;
        if (mi >= mloc) return;
        int W = widthp[0];
        int ind = locInd[mi];
        float wv = locw[ind];
        int r = ind - 1 - W;
        size_t rn = (size_t)r * n;
        float diag_r = 0.f;
        #pragma unroll
        for (int j = 0; j < 9; j++) {
            int off = (j / 3 - 1) + (j % 3 - 1) * W;
            int c = ind + off;
            float h = 0.5f * locFl[(size_t)j * 9 * mloc + mi] * wv;
            atomicAdd(&A[rn + c], -h);
            atomicAdd(&A[(size_t)c * n + r], -h);
            atomicAdd(&A[(size_t)c * n + c],  h);
            diag_r += h;
        }
        atomicAdd(&A[rn + r], diag_r);
        return;
    }
    b -= nbLoc;

    if (b < nbIu) {
        int mi = b * blockDim.x + threadIdx.x;
        if (mi >= miu) return;
        int r = iuInd[mi];
        float wv = iuw[r];
        size_t rn = (size_t)r * n;
        float diag_r = 0.f;
        #pragma unroll
        for (int j = 0; j < 5; j++) {
            float h = 0.5f * iuFl[mi * 5 + j] * wv;
            int c = iuNb[mi * 5 + j];
            atomicAdd(&A[rn + c], -h);
            atomicAdd(&A[(size_t)c * n + r], -h);
            atomicAdd(&A[(size_t)c * n + c],  h);
            diag_r += h;
        }
        atomicAdd(&A[rn + r], diag_r);
        return;
    }
    b -= nbIu;

    // diag regularization + b + scratch reset + tail-poison cleanup
    int i = b * blockDim.x + threadIdx.x;
    if (i < n) {
        float d = ku[i] * conf[i] + lmb[0] * known[i];
        atomicAdd(&A[(size_t)i * n + i], d);
        bvec[i] = d * kToU[i];
        g_cnt_row[i] = 0;
        g_rowsum[i]  = 0.f;
    }
    // zero any output elements beyond A (n*n) and b (n), if present
    long base = (long)n * n + n;
    long extra = total - base;
    if (extra > 0) {
        long p = (long)b * blockDim.x + threadIdx.x;
        if (p < extra) A[base + p] = 0.f;
    }
}

extern "C" void kernel_launch(void* const* d_in, const int* in_sizes, int n_in,
                              void* d_out, int out_size) {
    // 0 height, 1 width, 2 CM_weights, 3 LOC_weights, 4 IU_weights,
    // 5 KU_weights, 6 lmbda, 7 kToUconf, 8 known, 9 kToU,
    // 10 Wcm_row, 11 Wcm_col, 12 Wcm_data, 13 LOC_inInd, 14 LOC_flows,
    // 15 IU_inInd, 16 IU_flows, 17 IU_neighInd
    const int*   width   = (const int*)d_in[1];
    const float* CMw     = (const float*)d_in[2];
    const float* LOCw    = (const float*)d_in[3];
    const float* IUw     = (const float*)d_in[4];
    const float* KUw     = (const float*)d_in[5];
    const float* lmbda   = (const float*)d_in[6];
    const float* conf    = (const float*)d_in[7];
    const float* known   = (const float*)d_in[8];
    const float* kToU    = (const float*)d_in[9];
    const int*   wr      = (const int*)d_in[10];
    const int*   wc      = (const int*)d_in[11];
    const float* wd      = (const float*)d_in[12];
    const int*   locInd  = (const int*)d_in[13];
    const float* locFl   = (const float*)d_in[14];
    const int*   iuInd   = (const int*)d_in[15];
    const float* iuFl    = (const float*)d_in[16];
    const int*   iuNb    = (const int*)d_in[17];

    int N    = in_sizes[2];
    int NNZ  = in_sizes[10];
    int MLOC = in_sizes[13];
    int MIU  = in_sizes[15];

    float* A = (float*)d_out;
    float* b = A + (size_t)N * N;
    long total = (long)out_size;

    const int T = 256;
    k1_bin<<<(NNZ + T - 1) / T, T>>>(wr, wc, wd, CMw, NNZ);
    k2_rows<<<N, 512>>>(A, N);

    int nbLoc  = (MLOC + T - 1) / T;
    int nbIu   = (MIU + T - 1) / T;
    int nbDiag = (N + T - 1) / T;
    k3_rest<<<nbLoc + nbIu + nbDiag, T>>>(
        A, b, N, total,
        locInd, locFl, LOCw, MLOC, width,
        iuInd, iuFl, iuNb, IUw, MIU,
        KUw, conf, lmbda, known, kToU,
        nbLoc, nbIu);
}